// round 4
// baseline (speedup 1.0000x reference)
#include <cuda_runtime.h>
#include <math.h>
#include <stdint.h>

// SRBGCN: 2-layer hyperbolic GCN.
// Dominant cost: support = adj(16384x16384,fp32) @ msg(16384x32) per layer.
// tf32 mma.sync tensor GEMM, 4-stage cp.async pipeline (BM=64, BK=64),
// grid=256 CTAs (2/SM) for latency hiding. Fused Minkowski+selu+Poincare
// epilogue. HBM floor ~250us (2GB @ 8TB/s).

constexpr int NN     = 16384;
constexpr int D      = 32;
constexpr int BM     = 64;           // rows per CTA
constexpr int BK     = 64;           // k per stage
constexpr int STAGES = 4;
constexpr int NITER  = NN / BK;      // 256
constexpr int ADJ_FL = BM * BK;      // 4096 floats per adj stage
constexpr int MSG_FL = BK * D;       // 2048 floats per msg stage
constexpr int SMEM_BYTES = STAGES * (ADJ_FL + MSG_FL) * 4;  // 98304 (96KB)

// Scratch (static device arrays; no allocation allowed)
__device__ float g_M[2 * D * D];     // both layers' combined transforms
__device__ float g_msg[NN * D];
__device__ float g_x[NN * D];

// ---------------------------------------------------------------------------
__device__ __forceinline__ uint32_t smem_u32(const void* p) {
    return (uint32_t)__cvta_generic_to_shared(p);
}
__device__ __forceinline__ void cp_async16(uint32_t dst, const void* src) {
    asm volatile("cp.async.cg.shared.global [%0], [%1], 16;\n" :: "r"(dst), "l"(src));
}
__device__ __forceinline__ void cp_commit() {
    asm volatile("cp.async.commit_group;\n");
}
template <int N>
__device__ __forceinline__ void cp_wait() {
    asm volatile("cp.async.wait_group %0;\n" :: "n"(N));
}
__device__ __forceinline__ void mma_tf32(float* c,
                                         uint32_t a0, uint32_t a1, uint32_t a2, uint32_t a3,
                                         uint32_t b0, uint32_t b1) {
    asm volatile(
        "mma.sync.aligned.m16n8k8.row.col.f32.tf32.tf32.f32 "
        "{%0,%1,%2,%3}, {%4,%5,%6,%7}, {%8,%9}, {%0,%1,%2,%3};"
        : "+f"(c[0]), "+f"(c[1]), "+f"(c[2]), "+f"(c[3])
        : "r"(a0), "r"(a1), "r"(a2), "r"(a3), "r"(b0), "r"(b1));
}
__device__ __forceinline__ float to_tf32_rna(float x) {
    uint32_t r;
    asm("cvt.rna.tf32.f32 %0, %1;" : "=r"(r) : "f"(x));
    return __uint_as_float(r);
}

// ---------------------------------------------------------------------------
// Kernel 1: build both layers' combined transforms M_l[a][b] = sum_c LW[c][a]*LWh[c][b]
// grid=2 (blockIdx.x = layer), 1024 threads.
// ---------------------------------------------------------------------------
__global__ void build_M_kernel(const float* __restrict__ Ws,
                               const float* __restrict__ Hs) {
    const int layer = blockIdx.x;
    const float* W = Ws + layer * 31 * 31;
    const float* h = Hs + layer * 32;

    __shared__ float LWh[32][32];
    __shared__ float sc[3];

    int i = threadIdx.x >> 5;
    int j = threadIdx.x & 31;

    if (threadIdx.x == 0) {
        float ss = 0.f;
        for (int t = 1; t < 32; t++) { float v = h[t]; ss += v * v; }
        sc[0] = coshf(h[0]);
        sc[1] = sinhf(h[0]);
        sc[2] = rsqrtf(ss + 1e-14f);
    }
    __syncthreads();

    float ch = sc[0], sh = sc[1], invn = sc[2];
    float ni = (i >= 1) ? h[i] * invn : 0.f;
    float nj = (j >= 1) ? h[j] * invn : 0.f;

    float v;
    if (i == 0 && j == 0)      v = ch;
    else if (i == 0)           v = sh * nj;
    else if (j == 0)           v = sh * ni;
    else                       v = ((i == j) ? 1.f : 0.f) - (1.f - ch) * ni * nj;
    LWh[i][j] = v;
    __syncthreads();

    float m;
    if (i == 0) {
        m = LWh[0][j];
    } else {
        m = 0.f;
        for (int k = 1; k < 32; k++)
            m += W[(k - 1) * 31 + (i - 1)] * LWh[k][j];
    }
    g_M[layer * 1024 + i * 32 + j] = m;
}

// ---------------------------------------------------------------------------
// Kernel 2: msg = x @ M_l (16384x32 @ 32x32) -> g_msg (tf32-rounded).
// ---------------------------------------------------------------------------
__global__ void msg_kernel(const float* __restrict__ xin, int layer, int use_gx) {
    const float* x = use_gx ? g_x : xin;

    __shared__ float Ms[32 * 32];
    for (int t = threadIdx.x; t < 1024; t += blockDim.x)
        Ms[t] = g_M[layer * 1024 + t];
    __syncthreads();

    int gw   = (blockIdx.x * blockDim.x + threadIdx.x) >> 5;
    int lane = threadIdx.x & 31;
    if (gw >= NN) return;

    float xv  = x[(size_t)gw * D + lane];
    float acc = 0.f;
#pragma unroll
    for (int i = 0; i < 32; i++)
        acc = fmaf(__shfl_sync(0xffffffffu, xv, i), Ms[i * 32 + lane], acc);
    g_msg[(size_t)gw * D + lane] = to_tf32_rna(acc);
}

// ---------------------------------------------------------------------------
// Kernel 3: tf32 tensor GEMM support = adj @ g_msg + fused epilogue.
// 128 threads = 4 warps; warp w owns rows [w*16, w*16+16) of a 64-row tile.
// Per BK=64 stage: 8 k-steps x 4 n-tiles of m16n8k8.
// ---------------------------------------------------------------------------
__global__ __launch_bounds__(128)
void gemm_epi_kernel(const float* __restrict__ adj,
                     float* __restrict__ outp,
                     int write_gx) {
    extern __shared__ float smem[];
    float* adjs = smem;                      // STAGES * 4096 floats
    float* msgs = smem + STAGES * ADJ_FL;    // STAGES * 2048 floats

    const int tid  = threadIdx.x;
    const int lane = tid & 31;
    const int w    = tid >> 5;    // 0..3
    const int g    = lane >> 2;   // 0..7
    const int t    = lane & 3;    // 0..3
    const int row0 = blockIdx.x * BM;

    // ---- cp.async stage loader -------------------------------------------
    auto load_stage = [&](int it) {
        int kt = it * BK;
        int st = it % STAGES;
        float* as = adjs + st * ADJ_FL;
        float* ms = msgs + st * MSG_FL;
        // adj tile: 64 rows x 16 float4 (1024 float4; 8 per thread)
#pragma unroll
        for (int u = 0; u < 8; u++) {
            int idx = u * 128 + tid;
            int r   = idx >> 4;               // 0..63
            int c4  = idx & 15;               // float4 col
            const float* src = adj + (size_t)(row0 + r) * NN + kt + c4 * 4;
            cp_async16(smem_u32(as + (r * 16 + (c4 ^ (r & 15))) * 4), src);
        }
        // msg tile: 64 rows x 8 float4 (512 float4; 4 per thread)
#pragma unroll
        for (int u = 0; u < 4; u++) {
            int idx = u * 128 + tid;
            int r   = idx >> 3;               // 0..63
            int c4  = idx & 7;
            const float* src = g_msg + (size_t)(kt + r) * D + c4 * 4;
            cp_async16(smem_u32(ms + (r * 8 + (c4 ^ (r & 7))) * 4), src);
        }
        cp_commit();
    };

    // ---- prologue ----------------------------------------------------------
#pragma unroll
    for (int i = 0; i < STAGES - 1; i++) load_stage(i);

    float c[4][4];
#pragma unroll
    for (int nt = 0; nt < 4; nt++)
#pragma unroll
        for (int j = 0; j < 4; j++) c[nt][j] = 0.f;

    const int r0 = w * 16 + g;
    const int r1 = r0 + 8;

    // ---- main loop ----------------------------------------------------------
    for (int it = 0; it < NITER; it++) {
        cp_wait<STAGES - 2>();
        __syncthreads();
        if (it + STAGES - 1 < NITER) load_stage(it + STAGES - 1);

        const float* As = adjs + (it % STAGES) * ADJ_FL;
        const float* Bs = msgs + (it % STAGES) * MSG_FL;

#pragma unroll
        for (int ks = 0; ks < 8; ks++) {
            uint32_t a0 = __float_as_uint(As[(r0 * 16 + ((ks * 2)     ^ (r0 & 15))) * 4 + t]);
            uint32_t a1 = __float_as_uint(As[(r1 * 16 + ((ks * 2)     ^ (r1 & 15))) * 4 + t]);
            uint32_t a2 = __float_as_uint(As[(r0 * 16 + ((ks * 2 + 1) ^ (r0 & 15))) * 4 + t]);
            uint32_t a3 = __float_as_uint(As[(r1 * 16 + ((ks * 2 + 1) ^ (r1 & 15))) * 4 + t]);
            const int k0 = ks * 8 + t;
            const int k1 = k0 + 4;
#pragma unroll
            for (int nt = 0; nt < 4; nt++) {
                int n = nt * 8 + g;
                uint32_t b0 = __float_as_uint(Bs[(k0 * 8 + ((n >> 2) ^ (k0 & 7))) * 4 + (n & 3)]);
                uint32_t b1 = __float_as_uint(Bs[(k1 * 8 + ((n >> 2) ^ (k1 & 7))) * 4 + (n & 3)]);
                mma_tf32(c[nt], a0, a1, a2, a3, b0, b1);
            }
        }
        __syncthreads();
    }

    cp_wait<0>();
    __syncthreads();

    // ---- stage support rows into smem (reuse pipeline memory) --------------
    float* sup = smem;   // 64 rows x stride 33
#pragma unroll
    for (int nt = 0; nt < 4; nt++) {
        sup[r0 * 33 + nt * 8 + 2 * t]     = c[nt][0];
        sup[r0 * 33 + nt * 8 + 2 * t + 1] = c[nt][1];
        sup[r1 * 33 + nt * 8 + 2 * t]     = c[nt][2];
        sup[r1 * 33 + nt * 8 + 2 * t + 1] = c[nt][3];
    }
    __syncwarp();  // warp w reads exactly the rows warp w wrote

    // ---- fused epilogue: normalize + selu + Poincare ------------------------
    float* out = write_gx ? g_x : outp;
    for (int r = w * 16; r < w * 16 + 16; r++) {
        float s = sup[r * 33 + lane];

        float tt = s * s;
        float md = (lane == 0) ? -tt : tt;
#pragma unroll
        for (int o = 16; o; o >>= 1) md += __shfl_xor_sync(0xffffffffu, md, o);

        float denom = sqrtf(fmaxf(fabsf(md), 1e-8f));
        float xv    = s / denom;
        float x0    = __shfl_sync(0xffffffffu, xv, 0);

        float p = (lane == 0) ? 0.f : xv / (x0 + 1.f);
        const float alpha = 1.6732632423543772f;
        const float scale = 1.0507009873554805f;
        p = (p > 0.f) ? scale * p : scale * alpha * (expf(p) - 1.f);

        float pn = p * p;
#pragma unroll
        for (int o = 16; o; o >>= 1) pn += __shfl_xor_sync(0xffffffffu, pn, o);

        float inv  = 1.f / (1.f - pn);
        float outv = (lane == 0) ? (1.f + pn) * inv : 2.f * p * inv;
        out[(size_t)(row0 + r) * D + lane] = outv;
    }
}

// ---------------------------------------------------------------------------
extern "C" void kernel_launch(void* const* d_in, const int* in_sizes, int n_in,
                              void* d_out, int out_size) {
    const float* node = (const float*)d_in[0];  // 16384 x 32
    const float* adj  = (const float*)d_in[1];  // 16384 x 16384
    const float* Ws   = (const float*)d_in[2];  // 2 x 31 x 31
    const float* Hs   = (const float*)d_in[3];  // 2 x 32
    float* out = (float*)d_out;                 // 16384 x 32

    static bool attr_set = false;
    if (!attr_set) {
        cudaFuncSetAttribute(gemm_epi_kernel,
                             cudaFuncAttributeMaxDynamicSharedMemorySize, SMEM_BYTES);
        attr_set = true;
    }

    const int msg_blocks  = (NN * 32 + 255) / 256;
    const int gemm_blocks = NN / BM;   // 256

    build_M_kernel<<<2, 1024>>>(Ws, Hs);

    // Layer 0
    msg_kernel<<<msg_blocks, 256>>>(node, 0, 0);
    gemm_epi_kernel<<<gemm_blocks, 128, SMEM_BYTES>>>(adj, nullptr, 1);

    // Layer 1
    msg_kernel<<<msg_blocks, 256>>>(nullptr, 1, 1);
    gemm_epi_kernel<<<gemm_blocks, 128, SMEM_BYTES>>>(adj, out, 0);
}